// round 2
// baseline (speedup 1.0000x reference)
#include <cuda_runtime.h>

// ---------------- problem constants ----------------
#define NB 4
#define CDIM 384          // input channels
#define CQ 192            // DIM_Q
#define IH 256
#define IW 256
#define H2 128
#define W2 128
#define NHEADS 8
#define HD 24             // head dim
#define ATT_SCALE 0.2041241452319315f   // 24^-0.5

constexpr int HW  = IH * IW;   // 65536
constexpr int HW2 = H2 * W2;   // 16384

// ---------------- scratch (device globals; no runtime alloc) ----------------
__device__ float g_We[CDIM * CDIM];                       // DWT-folded kv weights: [kv_ch][c_rel*4+pos]
__device__ float g_qfeat[(size_t)NB * CQ * IH * IW];      // 201 MB
__device__ float g_kv[(size_t)NB * CDIM * H2 * W2];       // 100 MB: ch 0..191 = K, 192..383 = V
__device__ float g_feat[(size_t)NB * CQ * IH * IW];       // 201 MB

// ---------------- prep: fold Haar DWT into kv weights ----------------
// xd flat channel = c_idx*4 + sb; group g covers flat [g*384,(g+1)*384) ->
// c_idx in [g*96,(g+1)*96), local j = c_rel*4 + sb.
// We[ch][c_rel*4+pos] = sum_sb kv_w[ch][c_rel*4+sb] * H[sb][pos]
// H (x0.5): ll {+,+,+,+}  lh {-,-,+,+}  hl {-,+,-,+}  hh {+,-,-,+}
__global__ void prep_we_kernel(const float* __restrict__ kvw) {
    int idx = blockIdx.x * blockDim.x + threadIdx.x;
    if (idx >= CDIM * CDIM) return;
    int ch  = idx / CDIM;
    int rem = idx - ch * CDIM;
    int c4  = rem & ~3;
    int pos = rem & 3;
    const float* w = kvw + (size_t)ch * CDIM + c4;
    float a = w[0], b = w[1], c = w[2], d = w[3];   // ll, lh, hl, hh weights
    float r;
    if      (pos == 0) r = 0.5f * ( a - b - c + d);   // (dy,dx)=(0,0)
    else if (pos == 1) r = 0.5f * ( a - b + c - d);   // (0,1)
    else if (pos == 2) r = 0.5f * ( a + b - c - d);   // (1,0)
    else               r = 0.5f * ( a + b + c + d);   // (1,1)
    g_We[idx] = r;
}

// ---------------- generic SGEMM: Y[m,n] = sum_k W[m,k] X[k,n] (+bias) ----------------
// 64x128 tile, BK=16, 4x8 micro-tile, 256 threads. N mult of 128, M mult of 64, K mult of 16.
template<bool BIAS>
__global__ __launch_bounds__(256) void sgemm_kernel(
    const float* __restrict__ Wt, const float* __restrict__ X,
    float* __restrict__ Y, const float* __restrict__ bias,
    int M, int K, int N)
{
    constexpr int BM = 64, BN = 128, BK = 16, TM = 4, TN = 8;
    __shared__ float As[BK][BM];
    __shared__ float Bs[BK][BN];
    const int tid = threadIdx.x;
    const int tx = tid & 15, ty = tid >> 4;
    const int m0 = blockIdx.y * BM, n0 = blockIdx.x * BN;
    const float* Xb = X + (size_t)blockIdx.z * K * N;
    float* Yb = Y + (size_t)blockIdx.z * M * N;

    float acc[TM][TN] = {};

    const int arow = tid >> 2;          // 0..63
    const int akk  = (tid & 3) * 4;     // 0,4,8,12
    const float* aptr = Wt + (size_t)(m0 + arow) * K + akk;

    for (int k0 = 0; k0 < K; k0 += BK) {
        float4 av = *(const float4*)(aptr + k0);
        As[akk + 0][arow] = av.x;
        As[akk + 1][arow] = av.y;
        As[akk + 2][arow] = av.z;
        As[akk + 3][arow] = av.w;
        #pragma unroll
        for (int i = 0; i < 2; i++) {
            int f  = (tid + i * 256) * 4;
            int kr = f >> 7;
            int nc = f & 127;
            *(float4*)&Bs[kr][nc] =
                *(const float4*)(Xb + (size_t)(k0 + kr) * N + n0 + nc);
        }
        __syncthreads();
        #pragma unroll
        for (int kk = 0; kk < BK; kk++) {
            float4 a4 = *(const float4*)&As[kk][ty * TM];
            float4 b0 = *(const float4*)&Bs[kk][tx * TN];
            float4 b1 = *(const float4*)&Bs[kk][tx * TN + 4];
            float a[4]  = {a4.x, a4.y, a4.z, a4.w};
            float bv[8] = {b0.x, b0.y, b0.z, b0.w, b1.x, b1.y, b1.z, b1.w};
            #pragma unroll
            for (int i = 0; i < TM; i++)
                #pragma unroll
                for (int j = 0; j < TN; j++)
                    acc[i][j] = fmaf(a[i], bv[j], acc[i][j]);
        }
        __syncthreads();
    }
    #pragma unroll
    for (int i = 0; i < TM; i++) {
        int row = m0 + ty * TM + i;
        float bsv = BIAS ? bias[row] : 0.f;
        float* yp = Yb + (size_t)row * N + n0 + tx * TN;
        *(float4*)yp       = make_float4(acc[i][0] + bsv, acc[i][1] + bsv,
                                         acc[i][2] + bsv, acc[i][3] + bsv);
        *(float4*)(yp + 4) = make_float4(acc[i][4] + bsv, acc[i][5] + bsv,
                                         acc[i][6] + bsv, acc[i][7] + bsv);
    }
}

// ---------------- kv: grouped GEMM with fused DWT gather ----------------
// kv[b][g*96+o][y2][x2] = sum_{c_rel,pos} We[g*96+o][c_rel*4+pos] * x[b][g*96+c_rel][2y2+dy][2x2+dx]
// BM=96 (one group), BN=128 (= full W2 row -> y2 constant per block), BK=16, 6x8 micro-tile.
__global__ __launch_bounds__(256) void kv_kernel(const float* __restrict__ x,
                                                 float* __restrict__ kvout)
{
    constexpr int BM = 96, BN = 128, BK = 16, TM = 6, TN = 8;
    __shared__ float As[BK][BM];
    __shared__ float Bs[BK][BN];
    const int tid = threadIdx.x;
    const int tx = tid & 15, ty = tid >> 4;
    const int g = blockIdx.y, b = blockIdx.z;
    const int y2 = blockIdx.x;
    const float* xg = x + ((size_t)b * CDIM + g * 96) * HW;
    const float* Wg = g_We + (size_t)g * 96 * CDIM;
    float* Yb = kvout + ((size_t)b * CDIM + g * 96) * HW2;

    float acc[TM][TN] = {};
    for (int k0 = 0; k0 < CDIM; k0 += BK) {
        for (int i = tid; i < BM * BK; i += 256) {
            int row = i / BK, kk = i - row * BK;
            As[kk][row] = Wg[(size_t)row * CDIM + k0 + kk];
        }
        #pragma unroll
        for (int i = 0; i < 8; i++) {
            int f  = tid + i * 256;      // 0..2047
            int kr = f >> 7, nc = f & 127;
            int k    = k0 + kr;
            int crel = k >> 2, pos = k & 3;
            int yy = 2 * y2 + (pos >> 1);
            int xx = 2 * nc + (pos & 1);
            Bs[kr][nc] = xg[(size_t)crel * HW + yy * IW + xx];
        }
        __syncthreads();
        #pragma unroll
        for (int kk = 0; kk < BK; kk++) {
            float a[TM];
            #pragma unroll
            for (int i = 0; i < TM; i++) a[i] = As[kk][ty * TM + i];
            float4 b0 = *(const float4*)&Bs[kk][tx * TN];
            float4 b1 = *(const float4*)&Bs[kk][tx * TN + 4];
            float bv[8] = {b0.x, b0.y, b0.z, b0.w, b1.x, b1.y, b1.z, b1.w};
            #pragma unroll
            for (int i = 0; i < TM; i++)
                #pragma unroll
                for (int j = 0; j < TN; j++)
                    acc[i][j] = fmaf(a[i], bv[j], acc[i][j]);
        }
        __syncthreads();
    }
    #pragma unroll
    for (int i = 0; i < TM; i++) {
        int row = ty * TM + i;
        float* yp = Yb + (size_t)row * HW2 + y2 * W2 + tx * TN;
        *(float4*)yp       = make_float4(acc[i][0], acc[i][1], acc[i][2], acc[i][3]);
        *(float4*)(yp + 4) = make_float4(acc[i][4], acc[i][5], acc[i][6], acc[i][7]);
    }
}

// ---------------- attention: block per window; M = scale*K^T V, feat = q*M ----------------
// No softmax in reference -> attention is bilinear; M is 24x24 per (window, head).
__global__ __launch_bounds__(256) void attn_kernel()
{
    __shared__ float ks[16 * 193];                 // [t][ch] padded (193) for conflict-free
    __shared__ float vs[16 * 193];
    __shared__ float Ms[NHEADS * HD * HD];         // [head][e][d]
    const int w = blockIdx.x;
    const int b  = w >> 10;
    const int wl = w & 1023;
    const int wy = wl >> 5, wx = wl & 31;
    const int tid = threadIdx.x;

    const float* kvb = g_kv + (size_t)b * CDIM * HW2;
    for (int i = tid; i < CQ * 16; i += 256) {
        int ch = i >> 4, t = i & 15;
        int y2 = wy * 4 + (t >> 2), x2 = wx * 4 + (t & 3);
        size_t off = (size_t)ch * HW2 + y2 * W2 + x2;
        ks[t * 193 + ch] = kvb[off];
        vs[t * 193 + ch] = kvb[off + (size_t)CQ * HW2];
    }

    // q for this thread's pixel + 2 heads, in registers
    const int p = tid & 63, grp = tid >> 6;        // 64 pixels x 4 groups (2 heads each)
    const int y = wy * 8 + (p >> 3), x = wx * 8 + (p & 7);
    float qreg[48];
    const float* qb = g_qfeat + ((size_t)b * CQ + grp * 48) * HW + y * IW + x;
    #pragma unroll
    for (int c = 0; c < 48; c++) qreg[c] = qb[(size_t)c * HW];
    __syncthreads();

    // M[head][e][d] = scale * sum_t k[t][head*24+e] * v[t][head*24+d]
    for (int i = tid; i < NHEADS * HD * HD; i += 256) {
        int head = i / (HD * HD);
        int r = i - head * HD * HD;
        int e = r / HD, d = r - e * HD;
        const float* kp = ks + head * HD + e;
        const float* vp = vs + head * HD + d;
        float s = 0.f;
        #pragma unroll
        for (int t = 0; t < 16; t++)
            s = fmaf(kp[t * 193], vp[t * 193], s);
        Ms[i] = s * ATT_SCALE;
    }
    __syncthreads();

    // feat[head*24+d](pixel) = sum_e q[head*24+e] * M[head][e][d]
    float* fb = g_feat + ((size_t)b * CQ + grp * 48) * HW + y * IW + x;
    #pragma unroll
    for (int lh = 0; lh < 2; lh++) {
        int head = grp * 2 + lh;
        #pragma unroll
        for (int d = 0; d < HD; d++) {
            const float* mp = Ms + head * HD * HD + d;
            float s = 0.f;
            #pragma unroll
            for (int e = 0; e < HD; e++)
                s = fmaf(qreg[lh * HD + e], mp[e * HD], s);
            fb[(size_t)(lh * HD + d) * HW] = s;
        }
    }
}

// ---------------- launch ----------------
extern "C" void kernel_launch(void* const* d_in, const int* in_sizes, int n_in,
                              void* d_out, int out_size) {
    const float* x      = (const float*)d_in[0];
    const float* q_w    = (const float*)d_in[1];
    const float* kv_w   = (const float*)d_in[2];
    const float* proj_w = (const float*)d_in[3];
    const float* proj_b = (const float*)d_in[4];
    float* out = (float*)d_out;

    float *qf, *kv, *ft;
    cudaGetSymbolAddress((void**)&qf, g_qfeat);
    cudaGetSymbolAddress((void**)&kv, g_kv);
    cudaGetSymbolAddress((void**)&ft, g_feat);

    // 1. fold DWT into kv weights
    prep_we_kernel<<<(CDIM * CDIM + 255) / 256, 256>>>(kv_w);
    // 2. q_feat = q_w . x          (M=192, K=384, N=65536 per batch)
    sgemm_kernel<false><<<dim3(HW / 128, CQ / 64, NB), 256>>>(q_w, x, qf, nullptr, CQ, CDIM, HW);
    // 3. k,v = We . gather2x2(x)   (4 groups, M=96, K=384, N=16384 per batch)
    kv_kernel<<<dim3(H2, 4, NB), 256>>>(x, kv);
    // 4. per-window bilinear attention -> feat
    attn_kernel<<<NB * 1024, 256>>>();
    // 5. out = proj_w . feat + b   (M=384, K=192, N=65536 per batch)
    sgemm_kernel<true><<<dim3(HW / 128, CDIM / 64, NB), 256>>>(proj_w, ft, out, proj_b, CDIM, CQ, HW);
}

// round 5
// speedup vs baseline: 1.2714x; 1.2714x over previous
#include <cuda_runtime.h>
#include <cstdint>

// ---------------- problem constants ----------------
#define NB 4
#define CDIM 384
#define CQ 192
#define IH 256
#define IW 256
#define H2 128
#define W2 128
#define NHEADS 8
#define HD 24
#define ATT_SCALE 0.2041241452319315f   // 24^-0.5

constexpr int HW  = IH * IW;   // 65536
constexpr int HW2 = H2 * W2;   // 16384

// ---------------- scratch (device globals; no runtime alloc) ----------------
__device__ float g_We[CDIM * CDIM];
__device__ float g_qfeat[(size_t)NB * CQ * HW];
__device__ float g_kv[(size_t)NB * CDIM * HW2];
__device__ float g_feat[(size_t)NB * CQ * HW];

// ---------------- helpers ----------------
__device__ __forceinline__ uint32_t f2tf32(float f) {
    uint32_t r;
    asm("cvt.rna.tf32.f32 %0, %1;" : "=r"(r) : "f"(f));
    return r;
}

// m16n8k8 tf32 mma (baseline PTX, sm_80+ -> HMMA on sm_103)
__device__ __forceinline__ void mma8(float* c, const uint32_t* a, const uint32_t* b) {
    asm volatile(
        "mma.sync.aligned.m16n8k8.row.col.f32.tf32.tf32.f32 "
        "{%0,%1,%2,%3}, {%4,%5,%6,%7}, {%8,%9}, {%0,%1,%2,%3};"
        : "+f"(c[0]), "+f"(c[1]), "+f"(c[2]), "+f"(c[3])
        : "r"(a[0]), "r"(a[1]), "r"(a[2]), "r"(a[3]), "r"(b[0]), "r"(b[1]));
}

// ---------------- prep: fold Haar DWT into kv weights ----------------
__global__ void prep_we_kernel(const float* __restrict__ kvw) {
    int idx = blockIdx.x * blockDim.x + threadIdx.x;
    if (idx >= CDIM * CDIM) return;
    int ch  = idx / CDIM;
    int rem = idx - ch * CDIM;
    int c4  = rem & ~3;
    int pos = rem & 3;
    const float* w = kvw + (size_t)ch * CDIM + c4;
    float a = w[0], b = w[1], c = w[2], d = w[3];
    float r;
    if      (pos == 0) r = 0.5f * ( a - b - c + d);
    else if (pos == 1) r = 0.5f * ( a - b + c - d);
    else if (pos == 2) r = 0.5f * ( a + b - c - d);
    else               r = 0.5f * ( a + b + c + d);
    g_We[idx] = r;
}

// ---------------- tf32 mma.sync GEMM: Y[m,n] = sum_k W[m,k] X[k,n] (+bias) ----------------
// Block: BM x 64, BM = 48*WARPS_M covers all M rows of this launch's M-slice
// (activations read exactly once). BK=32 (4 k-steps of 8), smem double-buffered,
// operands stored in mma-fragment-canonical order (conflict-free lds.128/lds.64).
// MODE 0: X = [K, N] row-major. MODE 1: kv fused DWT gather from x.
template<int WARPS_M, int KTOT, int MODE, int MTOT, bool BIAS>
__global__ __launch_bounds__(256) void mma_gemm(
    const float* __restrict__ W, const float* __restrict__ X,
    float* __restrict__ Y, const float* __restrict__ bias, int N)
{
    constexpr int BM      = 48 * WARPS_M;
    constexpr int WARPS_N = 8 / WARPS_M;
    constexpr int WN      = 64 / WARPS_N;   // 32 or 16
    constexpr int NTW     = WN / 8;         // n8 tiles per warp: 4 or 2
    constexpr int MT      = 3;              // m16 tiles per warp (48 rows)
    constexpr int NCH     = KTOT / 32;
    constexpr int ANF     = BM / 32;        // float4 A loads per thread
    constexpr int AFL     = BM * 32;        // A floats per buffer
    constexpr int BUFL    = AFL + 2048;

    extern __shared__ __align__(16) float sm[];
    const int tid = threadIdx.x, wid = tid >> 5, lane = tid & 31;
    const int wm = wid / WARPS_N, wn = wid % WARPS_N;
    const int g = lane >> 2, tig = lane & 3;

    const float *Wp, *Xp;
    float* Yp;
    const float* bp = bias;
    int y2 = 0, xb = 0;
    const int n0 = blockIdx.x * 64;

    if (MODE == 0) {
        int b = blockIdx.z, moff = blockIdx.y * BM;
        Wp = W + (size_t)moff * KTOT;
        Xp = X + (size_t)b * KTOT * N;
        Yp = Y + ((size_t)b * MTOT + moff) * N;
        if (BIAS) bp = bias + moff;
    } else {
        int b = blockIdx.z >> 2, gg = blockIdx.z & 3;
        Wp = W + (size_t)gg * 96 * CDIM;
        Xp = X + ((size_t)b * CDIM + gg * 96) * HW;
        Yp = Y + ((size_t)b * CDIM + gg * 96) * HW2;
        y2 = n0 >> 7; xb = n0 & 127;
    }

    float acc[MT][NTW][4] = {};
    float4 aR[ANF];
    float4 bR[2];
    float  bS[8];

    auto loadG = [&](int c) {
        const int k0 = c * 32;
        #pragma unroll
        for (int i = 0; i < ANF; i++) {
            int e = tid + i * 256;
            int m = e >> 3, c4 = (e & 7) * 4;
            aR[i] = *(const float4*)(Wp + (size_t)m * KTOT + k0 + c4);
        }
        if (MODE == 0) {
            #pragma unroll
            for (int i = 0; i < 2; i++) {
                int e = tid + i * 256;
                int kr = e >> 4, n4 = (e & 15) * 4;
                bR[i] = *(const float4*)(Xp + (size_t)(k0 + kr) * N + n0 + n4);
            }
        } else {
            #pragma unroll
            for (int i = 0; i < 8; i++) {
                int e = tid + i * 256;
                int kr = e >> 6, n = e & 63;
                int k = k0 + kr;
                int crel = k >> 2, pos = k & 3;
                bS[i] = Xp[(size_t)crel * HW + (2 * y2 + (pos >> 1)) * IW
                           + 2 * (xb + n) + (pos & 1)];
            }
        }
    };

    auto storeS = [&](int buf) {
        float* As = sm + buf * BUFL;
        float* Bs = As + AFL;
        #pragma unroll
        for (int i = 0; i < ANF; i++) {
            int e = tid + i * 256;
            int m = e >> 3, c4 = (e & 7) * 4;
            int mt = m >> 4, rl = m & 7, rh = (m & 15) >> 3;
            int ks = c4 >> 3, kh = (c4 >> 2) & 1;
            uint32_t* dst = (uint32_t*)As + ((mt * 4 + ks) * 32 + rl * 4) * 4 + (rh | (kh << 1));
            float v[4] = {aR[i].x, aR[i].y, aR[i].z, aR[i].w};
            #pragma unroll
            for (int j = 0; j < 4; j++) dst[j * 4] = f2tf32(v[j]);
        }
        if (MODE == 0) {
            #pragma unroll
            for (int i = 0; i < 2; i++) {
                int e = tid + i * 256;
                int kr = e >> 4, n4 = (e & 15) * 4;
                int ks = kr >> 3, kk = kr & 7;
                int nt = n4 >> 3;
                uint32_t* dst = (uint32_t*)Bs
                    + ((nt * 4 + ks) * 32 + (n4 & 7) * 4 + (kk & 3)) * 2 + (kk >> 2);
                float v[4] = {bR[i].x, bR[i].y, bR[i].z, bR[i].w};
                #pragma unroll
                for (int j = 0; j < 4; j++) dst[j * 8] = f2tf32(v[j]);
            }
        } else {
            #pragma unroll
            for (int i = 0; i < 8; i++) {
                int e = tid + i * 256;
                int kr = e >> 6, n = e & 63;
                int ks = kr >> 3, kk = kr & 7;
                int nt = n >> 3, gg = n & 7;
                ((uint32_t*)Bs)[((nt * 4 + ks) * 32 + gg * 4 + (kk & 3)) * 2 + (kk >> 2)]
                    = f2tf32(bS[i]);
            }
        }
    };

    auto compute = [&](int buf) {
        const uint32_t* As = (const uint32_t*)(sm + buf * BUFL);
        const uint32_t* Bs = As + AFL;
        #pragma unroll
        for (int ks = 0; ks < 4; ks++) {
            uint32_t a[MT][4], b[NTW][2];
            #pragma unroll
            for (int i = 0; i < MT; i++) {
                int mt = wm * MT + i;
                uint4 v = *(const uint4*)(As + ((mt * 4 + ks) * 32 + lane) * 4);
                a[i][0] = v.x; a[i][1] = v.y; a[i][2] = v.z; a[i][3] = v.w;
            }
            #pragma unroll
            for (int j = 0; j < NTW; j++) {
                int nt = wn * NTW + j;
                uint2 v = *(const uint2*)(Bs + ((nt * 4 + ks) * 32 + lane) * 2);
                b[j][0] = v.x; b[j][1] = v.y;
            }
            #pragma unroll
            for (int i = 0; i < MT; i++)
                #pragma unroll
                for (int j = 0; j < NTW; j++)
                    mma8(acc[i][j], a[i], b[j]);
        }
    };

    loadG(0);
    storeS(0);
    __syncthreads();
    for (int c = 0; c < NCH; c++) {
        if (c + 1 < NCH) loadG(c + 1);
        compute(c & 1);
        if (c + 1 < NCH) {
            storeS((c + 1) & 1);
            __syncthreads();
        }
    }

    // epilogue
    const int mb = wm * 48;
    const int nb = n0 + wn * WN;
    #pragma unroll
    for (int i = 0; i < MT; i++) {
        int r0 = mb + i * 16 + g;
        float b0 = 0.f, b1 = 0.f;
        if (BIAS) { b0 = bp[r0]; b1 = bp[r0 + 8]; }
        #pragma unroll
        for (int j = 0; j < NTW; j++) {
            int nc = nb + j * 8 + tig * 2;
            *(float2*)(Yp + (size_t)r0 * N + nc) =
                make_float2(acc[i][j][0] + b0, acc[i][j][1] + b0);
            *(float2*)(Yp + (size_t)(r0 + 8) * N + nc) =
                make_float2(acc[i][j][2] + b1, acc[i][j][3] + b1);
        }
    }
}

// ---------------- attention: block per window; M = scale*K^T V, feat = q*M ----------------
__global__ __launch_bounds__(256) void attn_kernel()
{
    __shared__ float ks[16 * 193];
    __shared__ float vs[16 * 193];
    __shared__ float Ms[NHEADS * HD * HD];
    const int w = blockIdx.x;
    const int b  = w >> 10;
    const int wl = w & 1023;
    const int wy = wl >> 5, wx = wl & 31;
    const int tid = threadIdx.x;

    const float* kvb = g_kv + (size_t)b * CDIM * HW2;
    for (int i = tid; i < CQ * 16; i += 256) {
        int ch = i >> 4, t = i & 15;
        int y2 = wy * 4 + (t >> 2), x2 = wx * 4 + (t & 3);
        size_t off = (size_t)ch * HW2 + y2 * W2 + x2;
        ks[t * 193 + ch] = kvb[off];
        vs[t * 193 + ch] = kvb[off + (size_t)CQ * HW2];
    }

    const int p = tid & 63, grp = tid >> 6;
    const int y = wy * 8 + (p >> 3), x = wx * 8 + (p & 7);
    float qreg[48];
    const float* qb = g_qfeat + ((size_t)b * CQ + grp * 48) * HW + y * IW + x;
    #pragma unroll
    for (int c = 0; c < 48; c++) qreg[c] = qb[(size_t)c * HW];
    __syncthreads();

    for (int i = tid; i < NHEADS * HD * HD; i += 256) {
        int head = i / (HD * HD);
        int r = i - head * HD * HD;
        int e = r / HD, d = r - e * HD;
        const float* kp = ks + head * HD + e;
        const float* vp = vs + head * HD + d;
        float s = 0.f;
        #pragma unroll
        for (int t = 0; t < 16; t++)
            s = fmaf(kp[t * 193], vp[t * 193], s);
        Ms[i] = s * ATT_SCALE;
    }
    __syncthreads();

    float* fb = g_feat + ((size_t)b * CQ + grp * 48) * HW + y * IW + x;
    #pragma unroll
    for (int lh = 0; lh < 2; lh++) {
        int head = grp * 2 + lh;
        #pragma unroll
        for (int d = 0; d < HD; d++) {
            const float* mp = Ms + head * HD * HD + d;
            float s = 0.f;
            #pragma unroll
            for (int e = 0; e < HD; e++)
                s = fmaf(qreg[lh * HD + e], mp[e * HD], s);
            fb[(size_t)(lh * HD + d) * HW] = s;
        }
    }
}

// ---------------- launch ----------------
extern "C" void kernel_launch(void* const* d_in, const int* in_sizes, int n_in,
                              void* d_out, int out_size) {
    const float* x      = (const float*)d_in[0];
    const float* q_w    = (const float*)d_in[1];
    const float* kv_w   = (const float*)d_in[2];
    const float* proj_w = (const float*)d_in[3];
    const float* proj_b = (const float*)d_in[4];
    float* out = (float*)d_out;

    float *qf, *kv, *ft, *we;
    cudaGetSymbolAddress((void**)&qf, g_qfeat);
    cudaGetSymbolAddress((void**)&kv, g_kv);
    cudaGetSymbolAddress((void**)&ft, g_feat);
    cudaGetSymbolAddress((void**)&we, g_We);

    // q:    M=192 (BM=192), K=384
    auto kq = mma_gemm<4, 384, 0, 192, false>;
    // kv:   M=96  (BM=96),  K=384, fused DWT gather
    auto kk = mma_gemm<2, 384, 1, 96, false>;
    // proj: M=384 as 2 halves of BM=192, K=192, bias
    auto kp = mma_gemm<4, 192, 0, 384, true>;

    const int smem_q  = 2 * (192 * 32 + 2048) * 4;  // 65536
    const int smem_kv = 2 * ( 96 * 32 + 2048) * 4;  // 40960
    const int smem_pj = smem_q;                      // 65536
    cudaFuncSetAttribute(kq, cudaFuncAttributeMaxDynamicSharedMemorySize, smem_q);
    cudaFuncSetAttribute(kk, cudaFuncAttributeMaxDynamicSharedMemorySize, smem_kv);
    cudaFuncSetAttribute(kp, cudaFuncAttributeMaxDynamicSharedMemorySize, smem_pj);

    prep_we_kernel<<<(CDIM * CDIM + 255) / 256, 256>>>(kv_w);
    kq<<<dim3(HW / 64, 1, NB),   256, smem_q >>>(q_w, x, qf, nullptr, HW);
    kk<<<dim3(HW2 / 64, 1, NB * 4), 256, smem_kv>>>(we, x, kv, nullptr, HW2);
    attn_kernel<<<NB * 1024, 256>>>();
    kp<<<dim3(HW / 64, 2, NB),   256, smem_pj>>>(proj_w, ft, out, proj_b, HW);
}

// round 6
// speedup vs baseline: 3.4981x; 2.7513x over previous
#include <cuda_runtime.h>
#include <cstdint>

// ---------------- problem constants ----------------
#define NB 4
#define CDIM 384
#define CQ 192
#define IH 256
#define IW 256
#define H2 128
#define W2 128
#define NHEADS 8
#define HD 24
#define ATT_SCALE 0.2041241452319315f   // 24^-0.5

constexpr int HW  = IH * IW;   // 65536
constexpr int HW2 = H2 * W2;   // 16384

// ---------------- scratch (device globals; no runtime alloc) ----------------
__device__ float g_We[CDIM * CDIM];
__device__ float g_qfeat[(size_t)NB * CQ * HW];
__device__ float g_kv[(size_t)NB * CDIM * HW2];
__device__ float g_feat[(size_t)NB * CQ * HW];

// ---------------- helpers ----------------
__device__ __forceinline__ uint32_t f2tf32(float f) {
    uint32_t r;
    asm("cvt.rna.tf32.f32 %0, %1;" : "=r"(r) : "f"(f));
    return r;
}

// m16n8k8 tf32 mma (baseline PTX, sm_80+)
__device__ __forceinline__ void mma8(float* c, const uint32_t* a, const uint32_t* b) {
    asm volatile(
        "mma.sync.aligned.m16n8k8.row.col.f32.tf32.tf32.f32 "
        "{%0,%1,%2,%3}, {%4,%5,%6,%7}, {%8,%9}, {%0,%1,%2,%3};"
        : "+f"(c[0]), "+f"(c[1]), "+f"(c[2]), "+f"(c[3])
        : "r"(a[0]), "r"(a[1]), "r"(a[2]), "r"(a[3]), "r"(b[0]), "r"(b[1]));
}

// ---------------- prep: fold Haar DWT into kv weights ----------------
__global__ void prep_we_kernel(const float* __restrict__ kvw) {
    int idx = blockIdx.x * blockDim.x + threadIdx.x;
    if (idx >= CDIM * CDIM) return;
    int ch  = idx / CDIM;
    int rem = idx - ch * CDIM;
    int c4  = rem & ~3;
    int pos = rem & 3;
    const float* w = kvw + (size_t)ch * CDIM + c4;
    float a = w[0], b = w[1], c = w[2], d = w[3];
    float r;
    if      (pos == 0) r = 0.5f * ( a - b - c + d);
    else if (pos == 1) r = 0.5f * ( a - b + c - d);
    else if (pos == 2) r = 0.5f * ( a + b - c - d);
    else               r = 0.5f * ( a + b + c + d);
    g_We[idx] = r;
}

// ---------------- tf32 mma.sync GEMM: Y[m,n] = sum_k W[m,k] X[k,n] (+bias) ----------------
// A smem: [BM][36] (pad 36 -> fragment LDS banks 4g+tig: perfect permutation).
// B smem: [32][68] (pad 68 -> fragment LDS banks 4tig+g: conflict-free).
// All staging stores are contiguous STS.128 / stride-distinct STS.32 (conflict-free).
// MODE 0: X = [K, N] row-major. MODE 1: kv fused DWT gather (coalesced row loads).
template<int WARPS_M, int KTOT, int MODE, int MTOT, bool BIAS>
__global__ __launch_bounds__(256) void mma_gemm(
    const float* __restrict__ W, const float* __restrict__ X,
    float* __restrict__ Y, const float* __restrict__ bias, int N)
{
    constexpr int BM      = 48 * WARPS_M;
    constexpr int WARPS_N = 8 / WARPS_M;
    constexpr int WN      = 64 / WARPS_N;   // 32 or 16
    constexpr int NTW     = WN / 8;         // 4 or 2
    constexpr int MT      = 3;              // m16 tiles per warp (48 rows)
    constexpr int NCH     = KTOT / 32;
    constexpr int ANF     = BM / 32;        // float4 A loads per thread
    constexpr int AFL     = BM * 36;        // A floats per buffer (padded)
    constexpr int BUFL    = AFL + 32 * 68;  // + B floats (padded)

    extern __shared__ __align__(16) float sm[];
    const int tid = threadIdx.x, wid = tid >> 5, lane = tid & 31;
    const int wm = wid / WARPS_N, wn = wid % WARPS_N;
    const int g = lane >> 2, tig = lane & 3;

    const float *Wp, *Xp;
    float* Yp;
    const float* bp = bias;
    int y2 = 0, xb = 0;
    const int n0 = blockIdx.x * 64;

    if (MODE == 0) {
        int b = blockIdx.z, moff = blockIdx.y * BM;
        Wp = W + (size_t)moff * KTOT;
        Xp = X + (size_t)b * KTOT * N;
        Yp = Y + ((size_t)b * MTOT + moff) * N;
        if (BIAS) bp = bias + moff;
    } else {
        int b = blockIdx.z >> 2, gg = blockIdx.z & 3;
        Wp = W + (size_t)gg * 96 * CDIM;
        Xp = X + ((size_t)b * CDIM + gg * 96) * HW;
        Yp = Y + ((size_t)b * CDIM + gg * 96) * HW2;
        y2 = n0 >> 7; xb = n0 & 127;
    }

    float acc[MT][NTW][4] = {};
    float4 aR[ANF];
    float4 bR[2];
    float  bS[8];

    auto loadG = [&](int c) {
        const int k0 = c * 32;
        #pragma unroll
        for (int i = 0; i < ANF; i++) {
            int e = tid + i * 256;
            int m = e >> 3, c4 = (e & 7) * 4;
            aR[i] = *(const float4*)(Wp + (size_t)m * KTOT + k0 + c4);
        }
        if (MODE == 0) {
            #pragma unroll
            for (int i = 0; i < 2; i++) {
                int e = tid + i * 256;
                int kr = e >> 4, n4 = (e & 15) * 4;
                bR[i] = *(const float4*)(Xp + (size_t)(k0 + kr) * N + n0 + n4);
            }
        } else {
            // coalesced: 8 channels x 2 rows x 128 cols of x
            const int crel0 = k0 >> 2;
            #pragma unroll
            for (int i = 0; i < 8; i++) {
                int e = tid + i * 256;           // 0..2047
                int ch = e >> 8, row = (e >> 7) & 1, col = e & 127;
                bS[i] = Xp[(size_t)(crel0 + ch) * HW
                           + (2 * y2 + row) * IW + 2 * xb + col];
            }
        }
    };

    auto storeS = [&](int buf) {
        float* As = sm + buf * BUFL;
        float* Bs = As + AFL;
        #pragma unroll
        for (int i = 0; i < ANF; i++) {
            int e = tid + i * 256;
            int m = e >> 3, c4 = (e & 7) * 4;
            uint4 v;
            v.x = f2tf32(aR[i].x); v.y = f2tf32(aR[i].y);
            v.z = f2tf32(aR[i].z); v.w = f2tf32(aR[i].w);
            *(uint4*)((uint32_t*)As + m * 36 + c4) = v;
        }
        if (MODE == 0) {
            #pragma unroll
            for (int i = 0; i < 2; i++) {
                int e = tid + i * 256;
                int kr = e >> 4, n4 = (e & 15) * 4;
                uint4 v;
                v.x = f2tf32(bR[i].x); v.y = f2tf32(bR[i].y);
                v.z = f2tf32(bR[i].z); v.w = f2tf32(bR[i].w);
                *(uint4*)((uint32_t*)Bs + kr * 68 + n4) = v;
            }
        } else {
            #pragma unroll
            for (int i = 0; i < 8; i++) {
                int e = tid + i * 256;
                int ch = e >> 8, row = (e >> 7) & 1, col = e & 127;
                int k = ch * 4 + row * 2 + (col & 1);
                int n = col >> 1;
                ((uint32_t*)Bs)[k * 68 + n] = f2tf32(bS[i]);
            }
        }
    };

    auto compute = [&](int buf) {
        const uint32_t* As = (const uint32_t*)(sm + buf * BUFL);
        const uint32_t* Bs = As + AFL;
        #pragma unroll
        for (int ks = 0; ks < 4; ks++) {
            uint32_t a[MT][4], b[NTW][2];
            #pragma unroll
            for (int i = 0; i < MT; i++) {
                const uint32_t* p = As + (wm * 48 + i * 16 + g) * 36 + ks * 8 + tig;
                a[i][0] = p[0];
                a[i][1] = p[8 * 36];
                a[i][2] = p[4];
                a[i][3] = p[8 * 36 + 4];
            }
            #pragma unroll
            for (int j = 0; j < NTW; j++) {
                const uint32_t* p = Bs + (ks * 8 + tig) * 68 + wn * WN + j * 8 + g;
                b[j][0] = p[0];
                b[j][1] = p[4 * 68];
            }
            #pragma unroll
            for (int i = 0; i < MT; i++)
                #pragma unroll
                for (int j = 0; j < NTW; j++)
                    mma8(acc[i][j], a[i], b[j]);
        }
    };

    loadG(0);
    storeS(0);
    __syncthreads();
    for (int c = 0; c < NCH; c++) {
        if (c + 1 < NCH) loadG(c + 1);
        compute(c & 1);
        if (c + 1 < NCH) {
            storeS((c + 1) & 1);
            __syncthreads();
        }
    }

    // epilogue
    const int mb = wm * 48;
    const int nb = n0 + wn * WN;
    #pragma unroll
    for (int i = 0; i < MT; i++) {
        int r0 = mb + i * 16 + g;
        float b0 = 0.f, b1 = 0.f;
        if (BIAS) { b0 = bp[r0]; b1 = bp[r0 + 8]; }
        #pragma unroll
        for (int j = 0; j < NTW; j++) {
            int nc = nb + j * 8 + tig * 2;
            *(float2*)(Yp + (size_t)r0 * N + nc) =
                make_float2(acc[i][j][0] + b0, acc[i][j][1] + b0);
            *(float2*)(Yp + (size_t)(r0 + 8) * N + nc) =
                make_float2(acc[i][j][2] + b1, acc[i][j][3] + b1);
        }
    }
}

// ---------------- attention: bilinear, register-blocked ----------------
// Phase 2: M[h] = scale*K^T V (3e x 6d per thread).
// Phase 3: feat = q*M (4px x 12d per thread), q in smem, M broadcast loads.
constexpr int KS_F = 192 * 17;        // 3264 floats
constexpr int QS_F = 64 * 193;        // 12352
constexpr int MS_F = 24 * 200;        // 4800
constexpr int ATTN_SMEM = (2 * KS_F + QS_F + MS_F) * 4;   // 94720 B

__global__ __launch_bounds__(256, 2) void attn_kernel()
{
    extern __shared__ float sm[];
    float* ks = sm;
    float* vs = ks + KS_F;
    float* qs = vs + KS_F;
    float* Ms = qs + QS_F;

    const int w = blockIdx.x;
    const int b  = w >> 10;
    const int wl = w & 1023;
    const int wy = wl >> 5, wx = wl & 31;
    const int tid = threadIdx.x;

    // ---- load k, v : [ch][t] pitch 17 ----
    const float* kvb = g_kv + (size_t)b * CDIM * HW2;
    #pragma unroll
    for (int i = 0; i < 12; i++) {
        int e = tid + i * 256;
        int ch = e >> 4, t = e & 15;
        int y2 = wy * 4 + (t >> 2), x2 = wx * 4 + (t & 3);
        size_t off = (size_t)ch * HW2 + y2 * W2 + x2;
        ks[ch * 17 + t] = kvb[off];
        vs[ch * 17 + t] = kvb[off + (size_t)CQ * HW2];
    }
    // ---- load q : [p][ch] pitch 193 (float4 over x) ----
    const float* qb = g_qfeat + (size_t)b * CQ * HW;
    #pragma unroll
    for (int i = 0; i < 12; i++) {
        int e = tid + i * 256;
        int ch = e >> 4, pq = e & 15;
        int p = pq * 4;
        int y = wy * 8 + (p >> 3), x = wx * 8 + (p & 7);
        float4 v = *(const float4*)(qb + (size_t)ch * HW + y * IW + x);
        float* d = qs + p * 193 + ch;
        d[0] = v.x; d[193] = v.y; d[2 * 193] = v.z; d[3 * 193] = v.w;
    }
    __syncthreads();

    // ---- phase 2: Ms[e][h][d] (pitch: e*200 + h*25 + d) ----
    {
        const int h = tid >> 5, lane = tid & 31;
        const int e0 = (lane >> 2) * 3, d0 = (lane & 3) * 6;
        float acc[3][6] = {};
        const float* kp = ks + (h * 24 + e0) * 17;
        const float* vp = vs + (h * 24 + d0) * 17;
        #pragma unroll
        for (int t = 0; t < 16; t++) {
            float kk[3], vv[6];
            #pragma unroll
            for (int i = 0; i < 3; i++) kk[i] = kp[i * 17 + t];
            #pragma unroll
            for (int j = 0; j < 6; j++) vv[j] = vp[j * 17 + t];
            #pragma unroll
            for (int i = 0; i < 3; i++)
                #pragma unroll
                for (int j = 0; j < 6; j++)
                    acc[i][j] = fmaf(kk[i], vv[j], acc[i][j]);
        }
        #pragma unroll
        for (int i = 0; i < 3; i++)
            #pragma unroll
            for (int j = 0; j < 6; j++)
                Ms[(e0 + i) * 200 + h * 25 + d0 + j] = acc[i][j] * ATT_SCALE;
    }
    __syncthreads();

    // ---- phase 3: feat, 4px x 12d per thread ----
    {
        const int q4 = tid >> 4;
        const int h  = (tid >> 1) & 7;
        const int dh = tid & 1;
        const int p0 = q4 * 4;
        float acc[4][12] = {};
        const float* qp = qs + p0 * 193 + h * 24;
        const float* mp = Ms + h * 25 + dh * 12;
        #pragma unroll
        for (int e = 0; e < 24; e++) {
            float qv[4], mv[12];
            #pragma unroll
            for (int i = 0; i < 4; i++) qv[i] = qp[i * 193 + e];
            #pragma unroll
            for (int j = 0; j < 12; j++) mv[j] = mp[e * 200 + j];
            #pragma unroll
            for (int i = 0; i < 4; i++)
                #pragma unroll
                for (int j = 0; j < 12; j++)
                    acc[i][j] = fmaf(qv[i], mv[j], acc[i][j]);
        }
        const int y = wy * 8 + (p0 >> 3), x = wx * 8 + (p0 & 7);
        float* fb = g_feat + ((size_t)b * CQ + h * 24 + dh * 12) * HW + y * IW + x;
        #pragma unroll
        for (int j = 0; j < 12; j++) {
            *(float4*)(fb + (size_t)j * HW) =
                make_float4(acc[0][j], acc[1][j], acc[2][j], acc[3][j]);
        }
    }
}

// ---------------- launch ----------------
extern "C" void kernel_launch(void* const* d_in, const int* in_sizes, int n_in,
                              void* d_out, int out_size) {
    const float* x      = (const float*)d_in[0];
    const float* q_w    = (const float*)d_in[1];
    const float* kv_w   = (const float*)d_in[2];
    const float* proj_w = (const float*)d_in[3];
    const float* proj_b = (const float*)d_in[4];
    float* out = (float*)d_out;

    float *qf, *kv, *ft, *we;
    cudaGetSymbolAddress((void**)&qf, g_qfeat);
    cudaGetSymbolAddress((void**)&kv, g_kv);
    cudaGetSymbolAddress((void**)&ft, g_feat);
    cudaGetSymbolAddress((void**)&we, g_We);

    auto kq = mma_gemm<4, 384, 0, 192, false>;   // q:    BM=192, K=384
    auto kk = mma_gemm<2, 384, 1,  96, false>;   // kv:   BM=96,  K=384, DWT gather
    auto kp = mma_gemm<4, 192, 0, 384, true>;    // proj: 2 x BM=192, K=192, bias

    const int smem_q  = 2 * (192 * 36 + 32 * 68) * 4;  // 72704
    const int smem_kv = 2 * ( 96 * 36 + 32 * 68) * 4;  // 45056
    const int smem_pj = smem_q;
    cudaFuncSetAttribute(kq, cudaFuncAttributeMaxDynamicSharedMemorySize, smem_q);
    cudaFuncSetAttribute(kk, cudaFuncAttributeMaxDynamicSharedMemorySize, smem_kv);
    cudaFuncSetAttribute(kp, cudaFuncAttributeMaxDynamicSharedMemorySize, smem_pj);
    cudaFuncSetAttribute(attn_kernel, cudaFuncAttributeMaxDynamicSharedMemorySize, ATTN_SMEM);

    prep_we_kernel<<<(CDIM * CDIM + 255) / 256, 256>>>(kv_w);
    kq<<<dim3(HW / 64, 1, NB),      256, smem_q >>>(q_w, x, qf, nullptr, HW);
    kk<<<dim3(HW2 / 64, 1, NB * 4), 256, smem_kv>>>(we, x, kv, nullptr, HW2);
    attn_kernel<<<NB * 1024, 256, ATTN_SMEM>>>();
    kp<<<dim3(HW / 64, 2, NB),      256, smem_pj>>>(proj_w, ft, out, proj_b, HW);
}

// round 7
// speedup vs baseline: 3.7397x; 1.0691x over previous
#include <cuda_runtime.h>
#include <cstdint>

// ---------------- problem constants ----------------
#define NB 4
#define CDIM 384
#define CQ 192
#define IH 256
#define IW 256
#define H2 128
#define W2 128
#define NHEADS 8
#define HD 24
#define ATT_SCALE 0.2041241452319315f   // 24^-0.5

constexpr int HW  = IH * IW;   // 65536
constexpr int HW2 = H2 * W2;   // 16384

// ---------------- scratch (device globals; no runtime alloc) ----------------
__device__ float g_We[CDIM * CDIM];          // DWT-folded kv weights, tf32-rounded
__device__ float g_qw[CQ * CDIM];            // q weights, tf32-rounded
__device__ float g_pw[CDIM * CQ];            // proj weights, tf32-rounded
__device__ float g_qfeat[(size_t)NB * CQ * HW];
__device__ float g_kv[(size_t)NB * CDIM * HW2];
__device__ float g_feat[(size_t)NB * CQ * HW];

// ---------------- helpers ----------------
__device__ __forceinline__ uint32_t f2tf32(float f) {
    uint32_t r;
    asm("cvt.rna.tf32.f32 %0, %1;" : "=r"(r) : "f"(f));
    return r;
}
__device__ __forceinline__ uint32_t smem_u32(const void* p) {
    uint32_t a;
    asm("{ .reg .u64 t; cvta.to.shared.u64 t, %1; cvt.u32.u64 %0, t; }" : "=r"(a) : "l"(p));
    return a;
}
__device__ __forceinline__ void cp_async16(uint32_t dst, const float* src) {
    asm volatile("cp.async.ca.shared.global [%0], [%1], 16;"
                 :: "r"(dst), "l"(__cvta_generic_to_global(src)));
}
#define CP_COMMIT() asm volatile("cp.async.commit_group;" ::: "memory")
#define CP_WAIT0()  asm volatile("cp.async.wait_group 0;"  ::: "memory")

// m16n8k8 tf32 mma (baseline PTX, sm_80+)
__device__ __forceinline__ void mma8(float* c, const uint32_t* a, const uint32_t* b) {
    asm volatile(
        "mma.sync.aligned.m16n8k8.row.col.f32.tf32.tf32.f32 "
        "{%0,%1,%2,%3}, {%4,%5,%6,%7}, {%8,%9}, {%0,%1,%2,%3};"
        : "+f"(c[0]), "+f"(c[1]), "+f"(c[2]), "+f"(c[3])
        : "r"(a[0]), "r"(a[1]), "r"(a[2]), "r"(a[3]), "r"(b[0]), "r"(b[1]));
}

// ---------------- prep: fold Haar DWT into kv weights (tf32-rounded) ----------------
__global__ void prep_we_kernel(const float* __restrict__ kvw) {
    int idx = blockIdx.x * blockDim.x + threadIdx.x;
    if (idx >= CDIM * CDIM) return;
    int ch  = idx / CDIM;
    int rem = idx - ch * CDIM;
    int c4  = rem & ~3;
    int pos = rem & 3;
    const float* w = kvw + (size_t)ch * CDIM + c4;
    float a = w[0], b = w[1], c = w[2], d = w[3];
    float r;
    if      (pos == 0) r = 0.5f * ( a - b - c + d);
    else if (pos == 1) r = 0.5f * ( a - b + c - d);
    else if (pos == 2) r = 0.5f * ( a + b - c - d);
    else               r = 0.5f * ( a + b + c + d);
    g_We[idx] = __uint_as_float(f2tf32(r));
}

// ---------------- prep: tf32-round a weight matrix ----------------
__global__ void prep_cvt_kernel(const float* __restrict__ src, float* __restrict__ dst, int n) {
    int i = blockIdx.x * blockDim.x + threadIdx.x;
    if (i < n) dst[i] = __uint_as_float(f2tf32(src[i]));
}

// ---------------- tf32 mma.sync GEMM: Y[m,n] = sum_k W[m,k] X[k,n] (+bias) ----------------
// A (weights, pre-tf32): cp.async gmem->smem [BM][36] (no regs, no cvt).
// B: register-staged with cvt, smem [32][68]. Both layouts conflict-free.
// __launch_bounds__(256,2): 2 CTA/SM, 16 warps.
// MODE 0: X = [K, N] row-major. MODE 1: kv fused DWT gather (coalesced row loads).
template<int WARPS_M, int KTOT, int MODE, int MTOT, bool BIAS>
__global__ __launch_bounds__(256, 2) void mma_gemm(
    const float* __restrict__ Wt, const float* __restrict__ X,
    float* __restrict__ Y, const float* __restrict__ bias, int N)
{
    constexpr int BM      = 48 * WARPS_M;
    constexpr int WARPS_N = 8 / WARPS_M;
    constexpr int WN      = 64 / WARPS_N;   // 32 or 16
    constexpr int NTW     = WN / 8;         // 4 or 2
    constexpr int MT      = 3;
    constexpr int NCH     = KTOT / 32;
    constexpr int ANF     = BM / 32;        // 16B cp.async per thread for A
    constexpr int AFL     = BM * 36;
    constexpr int BUFL    = AFL + 32 * 68;

    extern __shared__ __align__(16) float sm[];
    const uint32_t sbase = smem_u32(sm);
    const int tid = threadIdx.x, wid = tid >> 5, lane = tid & 31;
    const int wm = wid / WARPS_N, wn = wid % WARPS_N;
    const int g = lane >> 2, tig = lane & 3;

    const float *Wp, *Xp;
    float* Yp;
    const float* bp = bias;
    int y2 = 0, xb = 0;
    const int n0 = blockIdx.x * 64;

    if (MODE == 0) {
        int b = blockIdx.z, moff = blockIdx.y * BM;
        Wp = Wt + (size_t)moff * KTOT;
        Xp = X + (size_t)b * KTOT * N;
        Yp = Y + ((size_t)b * MTOT + moff) * N;
        if (BIAS) bp = bias + moff;
    } else {
        int b = blockIdx.z >> 2, gg = blockIdx.z & 3;
        Wp = Wt + (size_t)gg * 96 * CDIM;
        Xp = X + ((size_t)b * CDIM + gg * 96) * HW;
        Yp = Y + ((size_t)b * CDIM + gg * 96) * HW2;
        y2 = n0 >> 7; xb = n0 & 127;
    }

    float acc[MT][NTW][4] = {};
    float4 bR[2];
    float  bS[8];

    auto loadA = [&](int c, int buf) {
        const int k0 = c * 32;
        const uint32_t As = sbase + (uint32_t)buf * BUFL * 4;
        #pragma unroll
        for (int i = 0; i < ANF; i++) {
            int e = tid + i * 256;
            int m = e >> 3, c4 = (e & 7) * 4;
            cp_async16(As + (m * 36 + c4) * 4, Wp + (size_t)m * KTOT + k0 + c4);
        }
        CP_COMMIT();
    };

    auto loadB = [&](int c) {
        const int k0 = c * 32;
        if (MODE == 0) {
            #pragma unroll
            for (int i = 0; i < 2; i++) {
                int e = tid + i * 256;
                int kr = e >> 4, n4 = (e & 15) * 4;
                bR[i] = *(const float4*)(Xp + (size_t)(k0 + kr) * N + n0 + n4);
            }
        } else {
            const int crel0 = k0 >> 2;
            #pragma unroll
            for (int i = 0; i < 8; i++) {
                int e = tid + i * 256;
                int ch = e >> 8, row = (e >> 7) & 1, col = e & 127;
                bS[i] = Xp[(size_t)(crel0 + ch) * HW
                           + (2 * y2 + row) * IW + 2 * xb + col];
            }
        }
    };

    auto storeB = [&](int buf) {
        uint32_t* Bs = (uint32_t*)(sm + buf * BUFL + AFL);
        if (MODE == 0) {
            #pragma unroll
            for (int i = 0; i < 2; i++) {
                int e = tid + i * 256;
                int kr = e >> 4, n4 = (e & 15) * 4;
                uint4 v;
                v.x = f2tf32(bR[i].x); v.y = f2tf32(bR[i].y);
                v.z = f2tf32(bR[i].z); v.w = f2tf32(bR[i].w);
                *(uint4*)(Bs + kr * 68 + n4) = v;
            }
        } else {
            #pragma unroll
            for (int i = 0; i < 8; i++) {
                int e = tid + i * 256;
                int ch = e >> 8, row = (e >> 7) & 1, col = e & 127;
                int k = ch * 4 + row * 2 + (col & 1);
                int n = col >> 1;
                Bs[k * 68 + n] = f2tf32(bS[i]);
            }
        }
    };

    auto compute = [&](int buf) {
        const uint32_t* As = (const uint32_t*)(sm + buf * BUFL);
        const uint32_t* Bs = As + AFL;
        #pragma unroll
        for (int ks = 0; ks < 4; ks++) {
            uint32_t a[MT][4], b[NTW][2];
            #pragma unroll
            for (int i = 0; i < MT; i++) {
                const uint32_t* p = As + (wm * 48 + i * 16 + g) * 36 + ks * 8 + tig;
                a[i][0] = p[0];
                a[i][1] = p[8 * 36];
                a[i][2] = p[4];
                a[i][3] = p[8 * 36 + 4];
            }
            #pragma unroll
            for (int j = 0; j < NTW; j++) {
                const uint32_t* p = Bs + (ks * 8 + tig) * 68 + wn * WN + j * 8 + g;
                b[j][0] = p[0];
                b[j][1] = p[4 * 68];
            }
            #pragma unroll
            for (int i = 0; i < MT; i++)
                #pragma unroll
                for (int j = 0; j < NTW; j++)
                    mma8(acc[i][j], a[i], b[j]);
        }
    };

    loadA(0, 0);
    loadB(0);
    storeB(0);
    CP_WAIT0();
    __syncthreads();
    for (int c = 0; c < NCH; c++) {
        if (c + 1 < NCH) { loadA(c + 1, (c + 1) & 1); loadB(c + 1); }
        compute(c & 1);
        if (c + 1 < NCH) {
            storeB((c + 1) & 1);
            CP_WAIT0();
            __syncthreads();
        }
    }

    // epilogue
    const int mb = wm * 48;
    const int nb = n0 + wn * WN;
    #pragma unroll
    for (int i = 0; i < MT; i++) {
        int r0 = mb + i * 16 + g;
        float b0 = 0.f, b1 = 0.f;
        if (BIAS) { b0 = bp[r0]; b1 = bp[r0 + 8]; }
        #pragma unroll
        for (int j = 0; j < NTW; j++) {
            int nc = nb + j * 8 + tig * 2;
            *(float2*)(Yp + (size_t)r0 * N + nc) =
                make_float2(acc[i][j][0] + b0, acc[i][j][1] + b0);
            *(float2*)(Yp + (size_t)(r0 + 8) * N + nc) =
                make_float2(acc[i][j][2] + b1, acc[i][j][3] + b1);
        }
    }
}

// ---------------- attention: bilinear, register-blocked ----------------
// Phase 2: M[h] = scale*K^T V (3e x 6d per thread), k/v in smem.
// Phase 3: feat = q*M (4px x 12d per thread), q direct from gmem (L2), Ms smem.
constexpr int KS_F = 192 * 17;        // 3264 floats
constexpr int MS_F = 24 * 200;        // 4800
constexpr int ATTN_SMEM = (2 * KS_F + MS_F) * 4;   // 45312 B

__global__ __launch_bounds__(256, 3) void attn_kernel()
{
    extern __shared__ float sm[];
    float* ks = sm;
    float* vs = ks + KS_F;
    float* Ms = vs + KS_F;

    const int w = blockIdx.x;
    const int b  = w >> 10;
    const int wl = w & 1023;
    const int wy = wl >> 5, wx = wl & 31;
    const int tid = threadIdx.x;

    // ---- load k, v : [ch][t] pitch 17 ----
    const float* kvb = g_kv + (size_t)b * CDIM * HW2;
    #pragma unroll
    for (int i = 0; i < 12; i++) {
        int e = tid + i * 256;
        int ch = e >> 4, t = e & 15;
        int y2 = wy * 4 + (t >> 2), x2 = wx * 4 + (t & 3);
        size_t off = (size_t)ch * HW2 + y2 * W2 + x2;
        ks[ch * 17 + t] = kvb[off];
        vs[ch * 17 + t] = kvb[off + (size_t)CQ * HW2];
    }
    __syncthreads();

    // ---- phase 2: Ms[e][h][d] (pitch: e*200 + h*25 + d) ----
    {
        const int h = tid >> 5, lane = tid & 31;
        const int e0 = (lane >> 2) * 3, d0 = (lane & 3) * 6;
        float acc[3][6] = {};
        const float* kp = ks + (h * 24 + e0) * 17;
        const float* vp = vs + (h * 24 + d0) * 17;
        #pragma unroll
        for (int t = 0; t < 16; t++) {
            float kk[3], vv[6];
            #pragma unroll
            for (int i = 0; i < 3; i++) kk[i] = kp[i * 17 + t];
            #pragma unroll
            for (int j = 0; j < 6; j++) vv[j] = vp[j * 17 + t];
            #pragma unroll
            for (int i = 0; i < 3; i++)
                #pragma unroll
                for (int j = 0; j < 6; j++)
                    acc[i][j] = fmaf(kk[i], vv[j], acc[i][j]);
        }
        #pragma unroll
        for (int i = 0; i < 3; i++)
            #pragma unroll
            for (int j = 0; j < 6; j++)
                Ms[(e0 + i) * 200 + h * 25 + d0 + j] = acc[i][j] * ATT_SCALE;
    }
    __syncthreads();

    // ---- phase 3: feat, 4px x 12d per thread, q streamed from gmem ----
    {
        const int q4 = tid >> 4;
        const int h  = (tid >> 1) & 7;
        const int dh = tid & 1;
        const int p0 = q4 * 4;
        const int y = wy * 8 + (p0 >> 3), x = wx * 8 + (p0 & 7);
        float acc[4][12] = {};
        const float* qp = g_qfeat + ((size_t)b * CQ + h * 24) * HW + y * IW + x;
        const float* mp = Ms + h * 25 + dh * 12;
        #pragma unroll
        for (int e = 0; e < 24; e++) {
            float4 qv = *(const float4*)(qp + (size_t)e * HW);
            float q0 = qv.x, q1 = qv.y, q2 = qv.z, q3 = qv.w;
            #pragma unroll
            for (int j = 0; j < 12; j++) {
                float mv = mp[e * 200 + j];
                acc[0][j] = fmaf(q0, mv, acc[0][j]);
                acc[1][j] = fmaf(q1, mv, acc[1][j]);
                acc[2][j] = fmaf(q2, mv, acc[2][j]);
                acc[3][j] = fmaf(q3, mv, acc[3][j]);
            }
        }
        float* fb = g_feat + ((size_t)b * CQ + h * 24 + dh * 12) * HW + y * IW + x;
        #pragma unroll
        for (int j = 0; j < 12; j++) {
            *(float4*)(fb + (size_t)j * HW) =
                make_float4(acc[0][j], acc[1][j], acc[2][j], acc[3][j]);
        }
    }
}

// ---------------- launch ----------------
extern "C" void kernel_launch(void* const* d_in, const int* in_sizes, int n_in,
                              void* d_out, int out_size) {
    const float* x      = (const float*)d_in[0];
    const float* q_w    = (const float*)d_in[1];
    const float* kv_w   = (const float*)d_in[2];
    const float* proj_w = (const float*)d_in[3];
    const float* proj_b = (const float*)d_in[4];
    float* out = (float*)d_out;

    float *qf, *kv, *ft, *we, *qw, *pw;
    cudaGetSymbolAddress((void**)&qf, g_qfeat);
    cudaGetSymbolAddress((void**)&kv, g_kv);
    cudaGetSymbolAddress((void**)&ft, g_feat);
    cudaGetSymbolAddress((void**)&we, g_We);
    cudaGetSymbolAddress((void**)&qw, g_qw);
    cudaGetSymbolAddress((void**)&pw, g_pw);

    auto kq = mma_gemm<4, 384, 0, 192, false>;   // q:    BM=192, K=384
    auto kk = mma_gemm<2, 384, 1,  96, false>;   // kv:   BM=96,  K=384, DWT gather
    auto kp = mma_gemm<4, 192, 0, 384, true>;    // proj: 2 x BM=192, K=192, bias

    const int smem_q  = 2 * (192 * 36 + 32 * 68) * 4;  // 72704
    const int smem_kv = 2 * ( 96 * 36 + 32 * 68) * 4;  // 45056
    const int smem_pj = smem_q;
    cudaFuncSetAttribute(kq, cudaFuncAttributeMaxDynamicSharedMemorySize, smem_q);
    cudaFuncSetAttribute(kk, cudaFuncAttributeMaxDynamicSharedMemorySize, smem_kv);
    cudaFuncSetAttribute(kp, cudaFuncAttributeMaxDynamicSharedMemorySize, smem_pj);
    cudaFuncSetAttribute(attn_kernel, cudaFuncAttributeMaxDynamicSharedMemorySize, ATTN_SMEM);

    prep_we_kernel<<<(CDIM * CDIM + 255) / 256, 256>>>(kv_w);
    prep_cvt_kernel<<<(CQ * CDIM + 255) / 256, 256>>>(q_w, qw, CQ * CDIM);
    prep_cvt_kernel<<<(CDIM * CQ + 255) / 256, 256>>>(proj_w, pw, CDIM * CQ);

    kq<<<dim3(HW / 64, 1, NB),      256, smem_q >>>(qw, x, qf, nullptr, HW);
    kk<<<dim3(HW2 / 64, 1, NB * 4), 256, smem_kv>>>(we, x, kv, nullptr, HW2);
    attn_kernel<<<NB * 1024, 256, ATTN_SMEM>>>();
    kp<<<dim3(HW / 64, 2, NB),      256, smem_pj>>>(pw, ft, out, proj_b, HW);
}